// round 1
// baseline (speedup 1.0000x reference)
#include <cuda_runtime.h>
#include <stdint.h>

#define BB      4
#define NN      16384
#define NPOINT  2048
#define CC      64
#define NSAMPLE 32
#define GRID    10
#define NCELLS  1024        // 10*10*10 = 1000, padded
#define R2      0.01f
#define CAND_CAP 256
#define OUTC    (CC + 3)    // 67

// scratch (static device globals; no allocation at runtime)
__device__ int   g_counts[BB * NCELLS];
__device__ int   g_starts[BB * NCELLS];
__device__ int   g_cursor[BB * NCELLS];
__device__ int   g_cell  [BB * NN];
__device__ int   g_order [BB * NN];
__device__ int   g_idx   [BB * NPOINT * NSAMPLE];
__device__ float g_ft    [BB * NN * CC];          // features transposed [B][N][C]

// ---------------------------------------------------------------- zero counts
__global__ void zero_counts_kernel() {
    int i = blockIdx.x * blockDim.x + threadIdx.x;
    if (i < BB * NCELLS) g_counts[i] = 0;
}

// ---------------------------------------------------------------- histogram
__global__ void hist_kernel(const float* __restrict__ xyz) {
    int i = blockIdx.x * blockDim.x + threadIdx.x;
    if (i >= BB * NN) return;
    float x = xyz[i * 3 + 0];
    float y = xyz[i * 3 + 1];
    float z = xyz[i * 3 + 2];
    int cx = (int)(x * 10.0f); cx = cx < 0 ? 0 : (cx > GRID - 1 ? GRID - 1 : cx);
    int cy = (int)(y * 10.0f); cy = cy < 0 ? 0 : (cy > GRID - 1 ? GRID - 1 : cy);
    int cz = (int)(z * 10.0f); cz = cz < 0 ? 0 : (cz > GRID - 1 ? GRID - 1 : cz);
    int cell = (cz * GRID + cy) * GRID + cx;
    int b = i / NN;
    g_cell[i] = cell;
    atomicAdd(&g_counts[b * NCELLS + cell], 1);
}

// ---------------------------------------------------------------- prefix scan (per batch)
__global__ void scan_kernel() {
    __shared__ int s[NCELLS];
    int b = blockIdx.x;
    int t = threadIdx.x;
    int v = g_counts[b * NCELLS + t];
    s[t] = v;
    __syncthreads();
    for (int off = 1; off < NCELLS; off <<= 1) {
        int x = 0;
        if (t >= off) x = s[t - off];
        __syncthreads();
        if (t >= off) s[t] += x;
        __syncthreads();
    }
    int excl = s[t] - v;
    g_starts[b * NCELLS + t] = excl;
    g_cursor[b * NCELLS + t] = excl;
}

// ---------------------------------------------------------------- scatter into cell order
__global__ void scatter_kernel() {
    int i = blockIdx.x * blockDim.x + threadIdx.x;
    if (i >= BB * NN) return;
    int b = i / NN;
    int cell = g_cell[i];
    int slot = atomicAdd(&g_cursor[b * NCELLS + cell], 1);
    g_order[b * NN + slot] = i - b * NN;
}

// ---------------------------------------------------------------- ball query (warp per query)
__global__ void __launch_bounds__(256) ballquery_kernel(
    const float* __restrict__ xyz, const float* __restrict__ new_xyz)
{
    __shared__ int buf_s[8][CAND_CAP];
    int warp = threadIdx.x >> 5;
    int lane = threadIdx.x & 31;
    int qid  = blockIdx.x * 8 + warp;
    int b = qid / NPOINT;
    int p = qid % NPOINT;

    float qx = new_xyz[qid * 3 + 0];
    float qy = new_xyz[qid * 3 + 1];
    float qz = new_xyz[qid * 3 + 2];
    int cx = (int)(qx * 10.0f); cx = cx < 0 ? 0 : (cx > GRID - 1 ? GRID - 1 : cx);
    int cy = (int)(qy * 10.0f); cy = cy < 0 ? 0 : (cy > GRID - 1 ? GRID - 1 : cy);
    int cz = (int)(qz * 10.0f); cz = cz < 0 ? 0 : (cz > GRID - 1 ? GRID - 1 : cz);

    int* buf = buf_s[warp];
    int cnt = 0;

    int z0 = cz > 0 ? cz - 1 : 0, z1 = cz < GRID - 1 ? cz + 1 : GRID - 1;
    int y0 = cy > 0 ? cy - 1 : 0, y1 = cy < GRID - 1 ? cy + 1 : GRID - 1;
    int x0 = cx > 0 ? cx - 1 : 0, x1 = cx < GRID - 1 ? cx + 1 : GRID - 1;

    for (int zc = z0; zc <= z1; zc++)
    for (int yc = y0; yc <= y1; yc++)
    for (int xc = x0; xc <= x1; xc++) {
        int cell = (zc * GRID + yc) * GRID + xc;
        int s0 = g_starts[b * NCELLS + cell];
        int cn = g_counts[b * NCELLS + cell];
        for (int j0 = 0; j0 < cn; j0 += 32) {
            int j = j0 + lane;
            bool valid = false;
            int pid = 0;
            if (j < cn) {
                pid = g_order[b * NN + s0 + j];
                const float* pp = xyz + ((size_t)(b * NN + pid)) * 3;
                float dx = qx - pp[0];
                float dy = qy - pp[1];
                float dz = qz - pp[2];
                valid = (dx * dx + dy * dy + dz * dz) < R2;
            }
            unsigned m = __ballot_sync(0xffffffffu, valid);
            int off = __popc(m & ((1u << lane) - 1));
            if (valid && (cnt + off) < CAND_CAP) buf[cnt + off] = pid;
            cnt += __popc(m);
            if (cnt > CAND_CAP) cnt = CAND_CAP;
        }
    }
    __syncwarp();

    if (cnt > 0) {
        int M = 32;
        while (M < cnt) M <<= 1;
        for (int i = cnt + lane; i < M; i += 32) buf[i] = 0x7fffffff;
        __syncwarp();
        for (int k = 2; k <= M; k <<= 1) {
            for (int j = k >> 1; j > 0; j >>= 1) {
                for (int i = lane; i < M; i += 32) {
                    int l = i ^ j;
                    if (l > i) {
                        int a = buf[i], c = buf[l];
                        bool up = ((i & k) == 0);
                        if ((a > c) == up) { buf[i] = c; buf[l] = a; }
                    }
                }
                __syncwarp();
            }
        }
    }
    __syncwarp();

    int outv;
    if (cnt == 0)            outv = 0;
    else if (lane < cnt)     outv = buf[lane];
    else                     outv = buf[0];
    g_idx[qid * NSAMPLE + lane] = outv;
}

// ---------------------------------------------------------------- feature transpose [B,C,N] -> [B,N,C]
__global__ void transpose_kernel(const float* __restrict__ f) {
    __shared__ float tile[32][33];
    int b  = blockIdx.z;
    int n0 = blockIdx.x * 32;
    int c0 = blockIdx.y * 32;
    int tx = threadIdx.x, ty = threadIdx.y;
#pragma unroll
    for (int k = 0; k < 32; k += 8)
        tile[ty + k][tx] = f[((size_t)(b * CC + c0 + ty + k)) * NN + n0 + tx];
    __syncthreads();
#pragma unroll
    for (int k = 0; k < 32; k += 8)
        g_ft[((size_t)(b * NN + n0 + ty + k)) * CC + c0 + tx] = tile[tx][ty + k];
}

// ---------------------------------------------------------------- grouping (block per query)
__global__ void __launch_bounds__(128) group_kernel(
    const float* __restrict__ xyz, const float* __restrict__ new_xyz,
    float* __restrict__ out)
{
    __shared__ int   sidx[NSAMPLE];
    __shared__ float T[NSAMPLE][OUTC];   // stride 67: conflict-free transposed reads

    int qid = blockIdx.x;
    int b = qid / NPOINT;
    int p = qid % NPOINT;
    int t = threadIdx.x;

    if (t < 32) sidx[t] = g_idx[qid * NSAMPLE + t];
    __syncthreads();

    // gather feature rows (256B each, contiguous) into registers
    int s4 = t >> 2, q = t & 3;
    const float4* row = (const float4*)(g_ft + ((size_t)(b * NN + sidx[s4])) * CC) + q * 4;
    float4 v0 = row[0];
    float4 v1 = row[1];
    float4 v2 = row[2];
    float4 v3 = row[3];

    // centered xyz channels
    float xv = 0.0f; int cxi = 0, sxi = 0;
    if (t < 96) {
        cxi = t >> 5; sxi = t & 31;
        xv = xyz[((size_t)(b * NN + sidx[sxi])) * 3 + cxi]
           - new_xyz[((size_t)(b * NPOINT + p)) * 3 + cxi];
    }

    // stage features into smem (scalar stores; conflict-free)
    float* dst = &T[s4][q * 16];
    dst[0]  = v0.x; dst[1]  = v0.y; dst[2]  = v0.z; dst[3]  = v0.w;
    dst[4]  = v1.x; dst[5]  = v1.y; dst[6]  = v1.z; dst[7]  = v1.w;
    dst[8]  = v2.x; dst[9]  = v2.y; dst[10] = v2.z; dst[11] = v2.w;
    dst[12] = v3.x; dst[13] = v3.y; dst[14] = v3.z; dst[15] = v3.w;
    __syncthreads();

    if (t < 96)
        out[(((size_t)b * OUTC + cxi) * NPOINT + p) * NSAMPLE + sxi] = xv;

    int s  = t & 31;
    int cb = t >> 5;   // 0..3
#pragma unroll
    for (int k = 0; k < 16; k++) {
        int c = cb * 16 + k;
        out[(((size_t)b * OUTC + 3 + c) * NPOINT + p) * NSAMPLE + s] = T[s][c];
    }
}

// ---------------------------------------------------------------- launch
extern "C" void kernel_launch(void* const* d_in, const int* in_sizes, int n_in,
                              void* d_out, int out_size)
{
    const float* xyz     = (const float*)d_in[0];
    const float* new_xyz = (const float*)d_in[1];
    const float* feat    = (const float*)d_in[2];
    float* out = (float*)d_out;

    zero_counts_kernel<<<(BB * NCELLS + 255) / 256, 256>>>();
    hist_kernel<<<(BB * NN + 255) / 256, 256>>>(xyz);
    scan_kernel<<<BB, NCELLS>>>();
    scatter_kernel<<<(BB * NN + 255) / 256, 256>>>();
    ballquery_kernel<<<(BB * NPOINT) / 8, 256>>>(xyz, new_xyz);
    transpose_kernel<<<dim3(NN / 32, CC / 32, BB), dim3(32, 8)>>>(feat);
    group_kernel<<<BB * NPOINT, 128>>>(xyz, new_xyz, out);
}

// round 2
// speedup vs baseline: 1.5201x; 1.5201x over previous
#include <cuda_runtime.h>
#include <stdint.h>

#define BB      4
#define NN      16384
#define NPOINT  2048
#define CC      64
#define NSAMPLE 32
#define GRID    10
#define NCELLS  1024        // 10*10*10 = 1000, padded
#define R2      0.01f
#define CAND_CAP 256
#define OUTC    (CC + 3)    // 67

#define BQ_BLOCKS   ((BB * NPOINT) / 8)            // 1024 blocks, 8 warps each
#define TR_BLOCKS   ((NN / 32) * (CC / 32) * BB)   // 512*2*4 = 4096

// scratch (static device globals; no allocation at runtime)
__device__ int    g_counts[BB * NCELLS];
__device__ int    g_starts[BB * NCELLS];
__device__ int    g_cellrank[BB * NN];             // (cell<<20)|rank
__device__ float4 g_pts  [BB * NN];                // cell-ordered {x,y,z,bitcast(pid)}
__device__ int    g_idx  [BB * NPOINT * NSAMPLE];
__device__ float  g_ft   [BB * NN * CC];           // features transposed [B][N][C]

// ---------------------------------------------------------------- histogram (+rank)
__global__ void hist_kernel(const float* __restrict__ xyz) {
    int i = blockIdx.x * blockDim.x + threadIdx.x;
    if (i >= BB * NN) return;
    float x = xyz[i * 3 + 0];
    float y = xyz[i * 3 + 1];
    float z = xyz[i * 3 + 2];
    int cx = (int)(x * 10.0f); cx = cx < 0 ? 0 : (cx > GRID - 1 ? GRID - 1 : cx);
    int cy = (int)(y * 10.0f); cy = cy < 0 ? 0 : (cy > GRID - 1 ? GRID - 1 : cy);
    int cz = (int)(z * 10.0f); cz = cz < 0 ? 0 : (cz > GRID - 1 ? GRID - 1 : cz);
    int cell = (cz * GRID + cy) * GRID + cx;
    int b = i / NN;
    int rank = atomicAdd(&g_counts[b * NCELLS + cell], 1);
    g_cellrank[i] = (cell << 20) | rank;
}

// ---------------------------------------------------------------- prefix scan (per batch)
__global__ void scan_kernel() {
    __shared__ int s[NCELLS];
    int b = blockIdx.x;
    int t = threadIdx.x;
    int v = g_counts[b * NCELLS + t];
    s[t] = v;
    __syncthreads();
    for (int off = 1; off < NCELLS; off <<= 1) {
        int x = 0;
        if (t >= off) x = s[t - off];
        __syncthreads();
        if (t >= off) s[t] += x;
        __syncthreads();
    }
    g_starts[b * NCELLS + t] = s[t] - v;   // exclusive
}

// ---------------------------------------------------------------- scatter (atomic-free), writes packed pts
__global__ void scatter_kernel(const float* __restrict__ xyz) {
    int i = blockIdx.x * blockDim.x + threadIdx.x;
    if (i >= BB * NN) return;
    int b = i / NN;
    int cr = g_cellrank[i];
    int cell = cr >> 20;
    int rank = cr & 0xfffff;
    int slot = g_starts[b * NCELLS + cell] + rank;
    float x = xyz[i * 3 + 0];
    float y = xyz[i * 3 + 1];
    float z = xyz[i * 3 + 2];
    g_pts[b * NN + slot] = make_float4(x, y, z, __int_as_float(i - b * NN));
}

// ---------------------------------------------------------------- fused: ballquery (warp/query) + feature transpose
__global__ void __launch_bounds__(256) bq_tr_kernel(
    const float* __restrict__ new_xyz, const float* __restrict__ feat)
{
    if (blockIdx.x >= BQ_BLOCKS) {
        // ---- transpose block: [B,C,N] -> [B,N,C]
        __shared__ float tile[32][33];
        int tb  = blockIdx.x - BQ_BLOCKS;
        int b   = tb / ((NN / 32) * (CC / 32));
        int rem = tb % ((NN / 32) * (CC / 32));
        int n0  = (rem % (NN / 32)) * 32;
        int c0  = (rem / (NN / 32)) * 32;
        int tx = threadIdx.x & 31, ty = threadIdx.x >> 5;   // ty 0..7
#pragma unroll
        for (int k = 0; k < 32; k += 8)
            tile[ty + k][tx] = feat[((size_t)(b * CC + c0 + ty + k)) * NN + n0 + tx];
        __syncthreads();
#pragma unroll
        for (int k = 0; k < 32; k += 8)
            g_ft[((size_t)(b * NN + n0 + ty + k)) * CC + c0 + tx] = tile[tx][ty + k];
        return;
    }

    // ---- ball query
    __shared__ int buf_s[8][CAND_CAP];
    int warp = threadIdx.x >> 5;
    int lane = threadIdx.x & 31;
    int qid  = blockIdx.x * 8 + warp;
    int b = qid / NPOINT;

    float qx = new_xyz[qid * 3 + 0];
    float qy = new_xyz[qid * 3 + 1];
    float qz = new_xyz[qid * 3 + 2];
    int cx = (int)(qx * 10.0f); cx = cx < 0 ? 0 : (cx > GRID - 1 ? GRID - 1 : cx);
    int cy = (int)(qy * 10.0f); cy = cy < 0 ? 0 : (cy > GRID - 1 ? GRID - 1 : cy);
    int cz = (int)(qz * 10.0f); cz = cz < 0 ? 0 : (cz > GRID - 1 ? GRID - 1 : cz);

    int* buf = buf_s[warp];
    int cnt = 0;

    int z0 = cz > 0 ? cz - 1 : 0, z1 = cz < GRID - 1 ? cz + 1 : GRID - 1;
    int y0 = cy > 0 ? cy - 1 : 0, y1 = cy < GRID - 1 ? cy + 1 : GRID - 1;
    int x0 = cx > 0 ? cx - 1 : 0, x1 = cx < GRID - 1 ? cx + 1 : GRID - 1;

    const float4* pts = g_pts + b * NN;
    const int* starts = g_starts + b * NCELLS;
    const int* counts = g_counts + b * NCELLS;

    for (int zc = z0; zc <= z1; zc++)
    for (int yc = y0; yc <= y1; yc++) {
        int base = (zc * GRID + yc) * GRID;
        int s0 = starts[base + x0];
        int e  = starts[base + x1] + counts[base + x1];   // x-cells are contiguous
        int len = e - s0;
        for (int j0 = 0; j0 < len; j0 += 32) {
            int j = j0 + lane;
            bool valid = false;
            int pid = 0;
            if (j < len) {
                float4 p = pts[s0 + j];
                float dx = qx - p.x;
                float dy = qy - p.y;
                float dz = qz - p.z;
                valid = (dx * dx + dy * dy + dz * dz) < R2;
                pid = __float_as_int(p.w);
            }
            unsigned m = __ballot_sync(0xffffffffu, valid);
            int off = __popc(m & ((1u << lane) - 1));
            if (valid && (cnt + off) < CAND_CAP) buf[cnt + off] = pid;
            cnt += __popc(m);
            if (cnt > CAND_CAP) cnt = CAND_CAP;
        }
    }
    __syncwarp();

    if (cnt > 0) {
        int M = 32;
        while (M < cnt) M <<= 1;
        for (int i = cnt + lane; i < M; i += 32) buf[i] = 0x7fffffff;
        __syncwarp();
        for (int k = 2; k <= M; k <<= 1) {
            for (int j = k >> 1; j > 0; j >>= 1) {
                for (int i = lane; i < M; i += 32) {
                    int l = i ^ j;
                    if (l > i) {
                        int a = buf[i], c = buf[l];
                        bool up = ((i & k) == 0);
                        if ((a > c) == up) { buf[i] = c; buf[l] = a; }
                    }
                }
                __syncwarp();
            }
        }
    }
    __syncwarp();

    int outv;
    if (cnt == 0)            outv = 0;
    else if (lane < cnt)     outv = buf[lane];
    else                     outv = buf[0];
    g_idx[qid * NSAMPLE + lane] = outv;
}

// ---------------------------------------------------------------- grouping (block per query)
__global__ void __launch_bounds__(128) group_kernel(
    const float* __restrict__ xyz, const float* __restrict__ new_xyz,
    float* __restrict__ out)
{
    __shared__ int   sidx[NSAMPLE];
    __shared__ float T[NSAMPLE][OUTC];   // stride 67: conflict-free transposed reads

    int qid = blockIdx.x;
    int b = qid / NPOINT;
    int p = qid % NPOINT;
    int t = threadIdx.x;

    if (t < 32) sidx[t] = g_idx[qid * NSAMPLE + t];
    __syncthreads();

    // gather feature rows (256B each, contiguous) into registers
    int s4 = t >> 2, q = t & 3;
    const float4* row = (const float4*)(g_ft + ((size_t)(b * NN + sidx[s4])) * CC) + q * 4;
    float4 v0 = row[0];
    float4 v1 = row[1];
    float4 v2 = row[2];
    float4 v3 = row[3];

    // centered xyz channels
    float xv = 0.0f; int cxi = 0, sxi = 0;
    if (t < 96) {
        cxi = t >> 5; sxi = t & 31;
        xv = xyz[((size_t)(b * NN + sidx[sxi])) * 3 + cxi]
           - new_xyz[((size_t)(b * NPOINT + p)) * 3 + cxi];
    }

    // stage features into smem
    float* dst = &T[s4][q * 16];
    dst[0]  = v0.x; dst[1]  = v0.y; dst[2]  = v0.z; dst[3]  = v0.w;
    dst[4]  = v1.x; dst[5]  = v1.y; dst[6]  = v1.z; dst[7]  = v1.w;
    dst[8]  = v2.x; dst[9]  = v2.y; dst[10] = v2.z; dst[11] = v2.w;
    dst[12] = v3.x; dst[13] = v3.y; dst[14] = v3.z; dst[15] = v3.w;
    __syncthreads();

    if (t < 96)
        out[(((size_t)b * OUTC + cxi) * NPOINT + p) * NSAMPLE + sxi] = xv;

    int s  = t & 31;
    int cb = t >> 5;   // 0..3
#pragma unroll
    for (int k = 0; k < 16; k++) {
        int c = cb * 16 + k;
        out[(((size_t)b * OUTC + 3 + c) * NPOINT + p) * NSAMPLE + s] = T[s][c];
    }
}

// ---------------------------------------------------------------- launch
extern "C" void kernel_launch(void* const* d_in, const int* in_sizes, int n_in,
                              void* d_out, int out_size)
{
    const float* xyz     = (const float*)d_in[0];
    const float* new_xyz = (const float*)d_in[1];
    const float* feat    = (const float*)d_in[2];
    float* out = (float*)d_out;

    void* counts_ptr = nullptr;
    cudaGetSymbolAddress(&counts_ptr, g_counts);
    cudaMemsetAsync(counts_ptr, 0, BB * NCELLS * sizeof(int), 0);

    hist_kernel<<<(BB * NN + 255) / 256, 256>>>(xyz);
    scan_kernel<<<BB, NCELLS>>>();
    scatter_kernel<<<(BB * NN + 255) / 256, 256>>>(xyz);
    bq_tr_kernel<<<BQ_BLOCKS + TR_BLOCKS, 256>>>(new_xyz, feat);
    group_kernel<<<BB * NPOINT, 128>>>(xyz, new_xyz, out);
}

// round 3
// speedup vs baseline: 2.0622x; 1.3566x over previous
#include <cuda_runtime.h>
#include <stdint.h>

#define BB      4
#define NN      16384
#define NPOINT  2048
#define CC      64
#define NSAMPLE 32
#define GRID    10
#define NCELLS  1024        // 10*10*10 = 1000, padded (pad cells scan to total)
#define R2      0.01f
#define CAND_CAP 192
#define OUTC    (CC + 3)    // 67

#define BQ_BLOCKS   ((BB * NPOINT) / 8)            // 1024 blocks, 8 warps each
#define TR_BLOCKS   ((NN / 32) * (CC / 32) * BB)   // 4096

// scratch (static device globals; no allocation at runtime)
__device__ int    g_counts[BB * NCELLS];
__device__ int    g_starts[BB * NCELLS];           // exclusive scan; starts[c+1] = end of c
__device__ int    g_cellrank[BB * NN];             // (cell<<20)|rank
__device__ float4 g_pts  [BB * NN];                // cell-ordered {x,y,z,bitcast(pid)}
__device__ int    g_idx  [BB * NPOINT * NSAMPLE];
__device__ float  g_ft   [BB * NN * CC];           // features transposed [B][N][C]

// ---------------------------------------------------------------- histogram (+rank)
__global__ void hist_kernel(const float* __restrict__ xyz) {
    int i = blockIdx.x * blockDim.x + threadIdx.x;
    if (i >= BB * NN) return;
    float x = xyz[i * 3 + 0];
    float y = xyz[i * 3 + 1];
    float z = xyz[i * 3 + 2];
    int cx = (int)(x * 10.0f); cx = cx < 0 ? 0 : (cx > GRID - 1 ? GRID - 1 : cx);
    int cy = (int)(y * 10.0f); cy = cy < 0 ? 0 : (cy > GRID - 1 ? GRID - 1 : cy);
    int cz = (int)(z * 10.0f); cz = cz < 0 ? 0 : (cz > GRID - 1 ? GRID - 1 : cz);
    int cell = (cz * GRID + cy) * GRID + cx;
    int b = i / NN;
    int rank = atomicAdd(&g_counts[b * NCELLS + cell], 1);
    g_cellrank[i] = (cell << 20) | rank;
}

// ---------------------------------------------------------------- prefix scan (per batch)
__global__ void scan_kernel() {
    __shared__ int s[NCELLS];
    int b = blockIdx.x;
    int t = threadIdx.x;
    int v = g_counts[b * NCELLS + t];
    s[t] = v;
    __syncthreads();
    for (int off = 1; off < NCELLS; off <<= 1) {
        int x = 0;
        if (t >= off) x = s[t - off];
        __syncthreads();
        if (t >= off) s[t] += x;
        __syncthreads();
    }
    g_starts[b * NCELLS + t] = s[t] - v;   // exclusive
}

// ---------------------------------------------------------------- scatter (atomic-free), writes packed pts
__global__ void scatter_kernel(const float* __restrict__ xyz) {
    int i = blockIdx.x * blockDim.x + threadIdx.x;
    if (i >= BB * NN) return;
    int b = i / NN;
    int cr = g_cellrank[i];
    int cell = cr >> 20;
    int rank = cr & 0xfffff;
    int slot = g_starts[b * NCELLS + cell] + rank;
    float x = xyz[i * 3 + 0];
    float y = xyz[i * 3 + 1];
    float z = xyz[i * 3 + 2];
    g_pts[b * NN + slot] = make_float4(x, y, z, __int_as_float(i - b * NN));
}

// ---------------------------------------------------------------- register bitonic helpers
__device__ __forceinline__ int bsort32(int v, int lane) {
#pragma unroll
    for (int k = 2; k <= 32; k <<= 1) {
#pragma unroll
        for (int j = k >> 1; j > 0; j >>= 1) {
            int p = __shfl_xor_sync(0xffffffffu, v, j);
            bool keep_min = ((lane & j) == 0) == ((lane & k) == 0);
            v = keep_min ? min(v, p) : max(v, p);
        }
    }
    return v;   // ascending across lanes
}

// ---------------------------------------------------------------- fused: ballquery (warp/query) + feature transpose
__global__ void __launch_bounds__(256) bq_tr_kernel(
    const float* __restrict__ new_xyz, const float* __restrict__ feat)
{
    if (blockIdx.x >= BQ_BLOCKS) {
        // ---- transpose block: [B,C,N] -> [B,N,C]
        __shared__ float tile[32][33];
        int tb  = blockIdx.x - BQ_BLOCKS;
        int b   = tb / ((NN / 32) * (CC / 32));
        int rem = tb % ((NN / 32) * (CC / 32));
        int n0  = (rem % (NN / 32)) * 32;
        int c0  = (rem / (NN / 32)) * 32;
        int tx = threadIdx.x & 31, ty = threadIdx.x >> 5;   // ty 0..7
#pragma unroll
        for (int k = 0; k < 32; k += 8)
            tile[ty + k][tx] = feat[((size_t)(b * CC + c0 + ty + k)) * NN + n0 + tx];
        __syncthreads();
#pragma unroll
        for (int k = 0; k < 32; k += 8)
            g_ft[((size_t)(b * NN + n0 + ty + k)) * CC + c0 + tx] = tile[tx][ty + k];
        return;
    }

    // ---- ball query
    __shared__ int buf_s[8][CAND_CAP];
    int warp = threadIdx.x >> 5;
    int lane = threadIdx.x & 31;
    int qid  = blockIdx.x * 8 + warp;
    int b = qid / NPOINT;

    float qx = new_xyz[qid * 3 + 0];
    float qy = new_xyz[qid * 3 + 1];
    float qz = new_xyz[qid * 3 + 2];
    int cx = (int)(qx * 10.0f); cx = cx < 0 ? 0 : (cx > GRID - 1 ? GRID - 1 : cx);
    int cy = (int)(qy * 10.0f); cy = cy < 0 ? 0 : (cy > GRID - 1 ? GRID - 1 : cy);
    int cz = (int)(qz * 10.0f); cz = cz < 0 ? 0 : (cz > GRID - 1 ? GRID - 1 : cz);

    int* buf = buf_s[warp];
    int cnt = 0;

    int z0 = cz > 0 ? cz - 1 : 0, z1 = cz < GRID - 1 ? cz + 1 : GRID - 1;
    int y0 = cy > 0 ? cy - 1 : 0, y1 = cy < GRID - 1 ? cy + 1 : GRID - 1;
    int x0 = cx > 0 ? cx - 1 : 0, x1 = cx < GRID - 1 ? cx + 1 : GRID - 1;

    const float4* pts = g_pts + b * NN;
    const int* starts = g_starts + b * NCELLS;

    for (int zc = z0; zc <= z1; zc++)
    for (int yc = y0; yc <= y1; yc++) {
        int base = (zc * GRID + yc) * GRID;
        int s0 = starts[base + x0];
        int e  = starts[base + x1 + 1];   // x-cells contiguous; next cell's start = end
        int len = e - s0;
        for (int j0 = 0; j0 < len; j0 += 32) {
            int j = j0 + lane;
            bool valid = false;
            int pid = 0;
            if (j < len) {
                float4 p = pts[s0 + j];
                float dx = qx - p.x;
                float dy = qy - p.y;
                float dz = qz - p.z;
                valid = (dx * dx + dy * dy + dz * dz) < R2;
                pid = __float_as_int(p.w);
            }
            unsigned m = __ballot_sync(0xffffffffu, valid);
            int off = __popc(m & ((1u << lane) - 1));
            if (valid && (cnt + off) < CAND_CAP) buf[cnt + off] = pid;
            cnt += __popc(m);
            if (cnt > CAND_CAP) cnt = CAND_CAP;
        }
    }
    __syncwarp();

    // ---- top-32 smallest (ascending) via register bitonic sort+merge
    int res = (lane < cnt) ? buf[lane] : 0x7fffffff;
    res = bsort32(res, lane);
    int nchunks = (cnt + 31) >> 5;
    for (int c = 1; c < nchunks; c++) {
        int idx = c * 32 + lane;
        int v = (idx < cnt) ? buf[idx] : 0x7fffffff;
        v = bsort32(v, lane);
        int vr = __shfl_sync(0xffffffffu, v, 31 - lane);   // reverse
        res = min(res, vr);                                 // bitonic, smallest 32
#pragma unroll
        for (int j = 16; j > 0; j >>= 1) {                  // clean
            int p = __shfl_xor_sync(0xffffffffu, res, j);
            res = ((lane & j) == 0) ? min(res, p) : max(res, p);
        }
    }
    int first = __shfl_sync(0xffffffffu, res, 0);
    int outv = (cnt == 0) ? 0 : ((lane < cnt) ? res : first);
    g_idx[qid * NSAMPLE + lane] = outv;
}

// ---------------------------------------------------------------- grouping (block per query)
__global__ void __launch_bounds__(128) group_kernel(
    const float* __restrict__ xyz, const float* __restrict__ new_xyz,
    float* __restrict__ out)
{
    __shared__ int   sidx[NSAMPLE];
    __shared__ float T[NSAMPLE][OUTC];   // stride 67: conflict-free transposed reads

    int qid = blockIdx.x;
    int b = qid / NPOINT;
    int p = qid % NPOINT;
    int t = threadIdx.x;

    if (t < 32) sidx[t] = g_idx[qid * NSAMPLE + t];
    __syncthreads();

    // gather feature rows (256B each, contiguous) into registers
    int s4 = t >> 2, q = t & 3;
    const float4* row = (const float4*)(g_ft + ((size_t)(b * NN + sidx[s4])) * CC) + q * 4;
    float4 v0 = row[0];
    float4 v1 = row[1];
    float4 v2 = row[2];
    float4 v3 = row[3];

    // centered xyz channels
    float xv = 0.0f; int cxi = 0, sxi = 0;
    if (t < 96) {
        cxi = t >> 5; sxi = t & 31;
        xv = xyz[((size_t)(b * NN + sidx[sxi])) * 3 + cxi]
           - new_xyz[((size_t)(b * NPOINT + p)) * 3 + cxi];
    }

    // stage features into smem
    float* dst = &T[s4][q * 16];
    dst[0]  = v0.x; dst[1]  = v0.y; dst[2]  = v0.z; dst[3]  = v0.w;
    dst[4]  = v1.x; dst[5]  = v1.y; dst[6]  = v1.z; dst[7]  = v1.w;
    dst[8]  = v2.x; dst[9]  = v2.y; dst[10] = v2.z; dst[11] = v2.w;
    dst[12] = v3.x; dst[13] = v3.y; dst[14] = v3.z; dst[15] = v3.w;
    __syncthreads();

    if (t < 96)
        out[(((size_t)b * OUTC + cxi) * NPOINT + p) * NSAMPLE + sxi] = xv;

    // feature output: float4 along sample dim, STG.128 coalesced
    // f = t + 128*k, k=0..3 ; c = f>>3 (0..63), sq = f&7 (sample quarter)
    float4* out4 = (float4*)(out + (((size_t)b * OUTC + 3) * NPOINT + p) * NSAMPLE);
#pragma unroll
    for (int k = 0; k < 4; k++) {
        int f  = t + 128 * k;
        int c  = f >> 3;
        int sq = f & 7;
        float4 w;
        w.x = T[4 * sq + 0][c];
        w.y = T[4 * sq + 1][c];
        w.z = T[4 * sq + 2][c];
        w.w = T[4 * sq + 3][c];
        out4[(size_t)c * (NPOINT * NSAMPLE / 4) + sq] = w;
    }
}

// ---------------------------------------------------------------- launch
extern "C" void kernel_launch(void* const* d_in, const int* in_sizes, int n_in,
                              void* d_out, int out_size)
{
    const float* xyz     = (const float*)d_in[0];
    const float* new_xyz = (const float*)d_in[1];
    const float* feat    = (const float*)d_in[2];
    float* out = (float*)d_out;

    void* counts_ptr = nullptr;
    cudaGetSymbolAddress(&counts_ptr, g_counts);
    cudaMemsetAsync(counts_ptr, 0, BB * NCELLS * sizeof(int), 0);

    hist_kernel<<<(BB * NN + 255) / 256, 256>>>(xyz);
    scan_kernel<<<BB, NCELLS>>>();
    scatter_kernel<<<(BB * NN + 255) / 256, 256>>>(xyz);
    bq_tr_kernel<<<BQ_BLOCKS + TR_BLOCKS, 256>>>(new_xyz, feat);
    group_kernel<<<BB * NPOINT, 128>>>(xyz, new_xyz, out);
}